// round 15
// baseline (speedup 1.0000x reference)
#include <cuda_runtime.h>
#include <cuda_bf16.h>

#define LAYERS 8
#define C 256
#define T 4096
#define B 16

typedef unsigned int u32;
typedef unsigned long long u64;

// ---------------- device global scratch (no allocation) ----------------
// activations, transposed [buf][b][t][ci], split hi/lo bf16 planes
__device__ __nv_bfloat16 g_zh[2][(size_t)B * T * C];
__device__ __nv_bfloat16 g_zl[2][(size_t)B * T * C];
// packed, PRE-SWIZZLED weights: [l][cb][ch][r=0..255][64]  (r = 2*co_local + conv)
__device__ __nv_bfloat16 g_wh[(size_t)LAYERS * 2 * 8 * 256 * 64];
__device__ __nv_bfloat16 g_wl[(size_t)LAYERS * 2 * 8 * 256 * 64];

// ---------------- helpers ----------------
__device__ __forceinline__ u32 smem_u32(const void* p) {
    u32 a;
    asm("{ .reg .u64 t; cvta.to.shared.u64 t, %1; cvt.u32.u64 %0, t; }" : "=r"(a) : "l"(p));
    return a;
}
__device__ __forceinline__ void split_bf(float v, __nv_bfloat16& h, __nv_bfloat16& l) {
    h = __float2bfloat16(v);
    l = __float2bfloat16(v - __bfloat162float(h));
}
__device__ __forceinline__ float actf(float f, float g) {
    float tf = 2.0f / (1.0f + __expf(-2.0f * f)) - 1.0f;
    float sg = 1.0f / (1.0f + __expf(-g));
    return tf * sg;
}
__device__ __forceinline__ void cpa(u32 dst, const void* src, u32 srcsz) {
    asm volatile("cp.async.cg.shared.global [%0], [%1], 16, %2;"
                 :: "r"(dst), "l"(src), "r"(srcsz) : "memory");
}
__device__ __forceinline__ void cpa_commit() {
    asm volatile("cp.async.commit_group;" ::: "memory");
}
__device__ __forceinline__ void ldsm4(u32& r0, u32& r1, u32& r2, u32& r3, u32 addr) {
    asm volatile("ldmatrix.sync.aligned.m8n8.x4.shared.b16 {%0,%1,%2,%3}, [%4];"
                 : "=r"(r0), "=r"(r1), "=r"(r2), "=r"(r3) : "r"(addr));
}
__device__ __forceinline__ void mma_bf16(float* d, const u32* a, const u32* b) {
    asm volatile("mma.sync.aligned.m16n8k16.row.col.f32.bf16.bf16.f32 "
                 "{%0,%1,%2,%3}, {%4,%5,%6,%7}, {%8,%9}, {%0,%1,%2,%3};"
                 : "+f"(d[0]), "+f"(d[1]), "+f"(d[2]), "+f"(d[3])
                 : "r"(a[0]), "r"(a[1]), "r"(a[2]), "r"(a[3]), "r"(b[0]), "r"(b[1]));
}

// ---------------- pre-kernels ----------------
// Pack weights: k = tap*256 + ci (tap0 = delayed), row r = 2*co_local + conv,
// SW128 swizzle baked into the 64-element row (elem col = kc ^ ((r&7)<<3)).
__global__ void cvt_weights(const float* __restrict__ fw, const float* __restrict__ gw) {
    int idx = blockIdx.x * 256 + threadIdx.x;
    if (idx >= LAYERS * C * C * 2) return;
    int tap = idx & 1;
    int ci = (idx >> 1) & 255;
    int co = (idx >> 9) & 255;
    int l  = idx >> 17;
    int k  = tap * 256 + ci;
    int ch = k >> 6, kc = k & 63;
    int cb = co >> 7;
    #pragma unroll
    for (int conv = 0; conv < 2; conv++) {
        int r = ((co & 127) << 1) | conv;
        size_t dst = (((size_t)(l * 2 + cb) * 8 + ch) * 256 + r) * 64
                   + (kc ^ ((r & 7) << 3));
        float v = conv ? gw[idx] : fw[idx];
        split_bf(v, g_wh[dst], g_wl[dst]);
    }
}

// Transpose ys [b][c][t] -> g_z[0][b][t][c] split hi/lo.
__global__ void cvt_x(const float* __restrict__ ys) {
    __shared__ float tile[32][33];
    int b = blockIdx.z, t0 = blockIdx.x * 32, c0 = blockIdx.y * 32;
    int tx = threadIdx.x, ty = threadIdx.y;
    #pragma unroll
    for (int i = 0; i < 4; i++) {
        int cc = ty + i * 8;
        tile[cc][tx] = ys[((size_t)b * C + c0 + cc) * T + t0 + tx];
    }
    __syncthreads();
    #pragma unroll
    for (int i = 0; i < 4; i++) {
        int tt = ty + i * 8;
        size_t off = ((size_t)b * T + t0 + tt) * C + c0 + tx;
        split_bf(tile[tx][tt], g_zh[0][off], g_zl[0][off]);
    }
}

// ---------------- main layer kernel ----------------
// CTA: M=256 rows (128 co x {F,G} interleaved) x N=128 t, K=512 in 8 chunks of 64.
// 256 threads, 8 warps as 4m x 2n, warp tile 64x64 (mi=4, ni=8), acc=128 regs.
// SMEM per stage: Ah 32K | Al 32K | Bh 16K | Bl 16K = 96K, double buffered.
#define STAGE_BYTES 98304
#define SMEM_TOTAL (2 * STAGE_BYTES)

__global__ __launch_bounds__(256, 1)
void wn_gemm(const float* __restrict__ fb, const float* __restrict__ gb,
             float* __restrict__ out,
             int rd, int l, int d, int first, int wnext)
{
    extern __shared__ __align__(1024) char smem[];
    const u32 sb = smem_u32(smem);
    const int tid = threadIdx.x;
    const int lane = tid & 31, wid = tid >> 5;
    const int wm = wid & 3, wn = wid >> 2;      // 4 m-warps x 2 n-warps
    const int t0 = blockIdx.x * 128;
    const int b  = blockIdx.y;
    const int cb = blockIdx.z;
    const int co0 = cb * 128;

    const __nv_bfloat16* xh = g_zh[rd];
    const __nv_bfloat16* xl = g_zl[rd];

    float acc[4][8][4];
    #pragma unroll
    for (int mi = 0; mi < 4; mi++)
        #pragma unroll
        for (int ni = 0; ni < 8; ni++)
            #pragma unroll
            for (int e = 0; e < 4; e++) acc[mi][ni][e] = 0.0f;

    // ---- stage loader (256 threads) ----
    const size_t wblob = (size_t)(l * 2 + cb) * 8 * 16384;
    const int brow = tid >> 1;            // 0..127 (t row)
    const int bc0  = (tid & 1) * 4;       // 4 chunks of 16B per plane

    auto load_stage = [&](int ch, int s) {
        const u32 base = sb + s * STAGE_BYTES;
        // A: linear copy of pre-swizzled 32KB blobs (hi & lo)
        const char* gah = (const char*)(g_wh + wblob + (size_t)ch * 16384);
        const char* gal = (const char*)(g_wl + wblob + (size_t)ch * 16384);
        #pragma unroll
        for (int j = 0; j < 8; j++) {
            int off = (tid + j * 256) * 16;
            cpa(base + off,         gah + off, 16);
            cpa(base + 32768 + off, gal + off, 16);
        }
        // B: X[t rows][64 ci] with SW128 swizzle; delayed tap shifts rows by -d
        const int delayed = (ch < 4);
        const int ci0 = (ch & 3) * 64;
        const int trow = t0 + brow - (delayed ? d : 0);
        const u32 ssz = (trow >= 0) ? 16u : 0u;
        const int trc = (trow >= 0) ? trow : 0;
        const size_t go = ((size_t)b * T + trc) * C + ci0;
        #pragma unroll
        for (int j = 0; j < 4; j++) {
            int c = bc0 + j;
            u32 doff = brow * 128 + ((c * 16) ^ ((brow & 7) << 4));
            cpa(base + 65536 + doff, (const char*)(xh + go + c * 8), ssz);
            cpa(base + 81920 + doff, (const char*)(xl + go + c * 8), ssz);
        }
    };

    // lane-invariant fragment addressing
    const int rA = (lane & 7) + (lane & 8);          // A row within m16
    const int cAh = (lane >> 4);                     // A 16B chunk half
    const int rB = (lane & 7) + ((lane >> 4) << 3);  // B row within n16
    const int cBh = ((lane >> 3) & 1);               // B 16B chunk half

    auto compute = [&](u32 base) {
        const u32 Ah = base, Al = base + 32768, Bh = base + 65536, Bl = base + 81920;
        // K chunk is 64 wide = FOUR k16 blocks.
        #pragma unroll
        for (int ks = 0; ks < 4; ks++) {
            u32 bfr[8][2], ah[4][4], al[4][4];
            const int cB = ks * 2 + cBh;
            const int cA = ks * 2 + cAh;
            // B hi frags: 4 x ldmatrix.x4 covering n 0..63
            #pragma unroll
            for (int g = 0; g < 4; g++) {
                int row = wn * 64 + g * 16 + rB;
                u32 ad = Bh + row * 128 + ((cB * 16) ^ ((row & 7) << 4));
                ldsm4(bfr[2 * g][0], bfr[2 * g][1], bfr[2 * g + 1][0], bfr[2 * g + 1][1], ad);
            }
            // A hi frags (m64)
            #pragma unroll
            for (int mi = 0; mi < 4; mi++) {
                int row = wm * 64 + mi * 16 + rA;
                u32 ad = Ah + row * 128 + ((cA * 16) ^ ((row & 7) << 4));
                ldsm4(ah[mi][0], ah[mi][1], ah[mi][2], ah[mi][3], ad);
            }
            // hh
            #pragma unroll
            for (int mi = 0; mi < 4; mi++)
                #pragma unroll
                for (int ni = 0; ni < 8; ni++) mma_bf16(acc[mi][ni], ah[mi], bfr[ni]);
            // A lo frags -> lh
            #pragma unroll
            for (int mi = 0; mi < 4; mi++) {
                int row = wm * 64 + mi * 16 + rA;
                u32 ad = Al + row * 128 + ((cA * 16) ^ ((row & 7) << 4));
                ldsm4(al[mi][0], al[mi][1], al[mi][2], al[mi][3], ad);
            }
            #pragma unroll
            for (int mi = 0; mi < 4; mi++)
                #pragma unroll
                for (int ni = 0; ni < 8; ni++) mma_bf16(acc[mi][ni], al[mi], bfr[ni]);
            // B lo frags (reuse regs) -> hl
            #pragma unroll
            for (int g = 0; g < 4; g++) {
                int row = wn * 64 + g * 16 + rB;
                u32 ad = Bl + row * 128 + ((cB * 16) ^ ((row & 7) << 4));
                ldsm4(bfr[2 * g][0], bfr[2 * g][1], bfr[2 * g + 1][0], bfr[2 * g + 1][1], ad);
            }
            #pragma unroll
            for (int mi = 0; mi < 4; mi++)
                #pragma unroll
                for (int ni = 0; ni < 8; ni++) mma_bf16(acc[mi][ni], ah[mi], bfr[ni]);
        }
    };

    // ---- pipelined main loop (not unrolled: keep I-footprint small) ----
    load_stage(0, 0); cpa_commit();
    load_stage(1, 1); cpa_commit();
    #pragma unroll 1
    for (int ch = 0; ch < 8; ch++) {
        asm volatile("cp.async.wait_group 1;" ::: "memory");
        __syncthreads();
        compute(sb + (ch & 1) * STAGE_BYTES);
        __syncthreads();
        if (ch + 2 < 8) load_stage(ch + 2, ch & 1);
        cpa_commit();
    }

    // ---- epilogue: pair F/G via shfl_xor(4), act, write Zout + next Z ----
    __nv_bfloat16* zh = g_zh[rd ^ 1];
    __nv_bfloat16* zl = g_zl[rd ^ 1];
    const int q = lane >> 2;
    const int tcol = t0 + wn * 64 + (lane & 3) * 2;
    const int qodd = q & 1;
    #pragma unroll
    for (int mi = 0; mi < 4; mi++) {
        const int co = co0 + wm * 32 + mi * 8 + (q >> 1) + qodd * 4;
        const float fbv = __ldg(fb + co);
        const float gbv = __ldg(gb + co);
        #pragma unroll
        for (int ni = 0; ni < 8; ni++) {
            float p0 = __shfl_xor_sync(0xffffffffu, acc[mi][ni][0], 4);
            float p1 = __shfl_xor_sync(0xffffffffu, acc[mi][ni][1], 4);
            float p2 = __shfl_xor_sync(0xffffffffu, acc[mi][ni][2], 4);
            float p3 = __shfl_xor_sync(0xffffffffu, acc[mi][ni][3], 4);
            // even q: rows (q, q+1): F = own d0,d1; G = partner d0,d1
            // odd  q: rows (q+7, q+8): F = partner d2,d3; G = own d2,d3
            float f0, f1, g0, g1;
            if (!qodd) { f0 = acc[mi][ni][0]; f1 = acc[mi][ni][1]; g0 = p0; g1 = p1; }
            else       { f0 = p2; f1 = p3; g0 = acc[mi][ni][2]; g1 = acc[mi][ni][3]; }
            const int t = tcol + ni * 8;
            float z0 = actf(f0 + fbv, g0 + gbv);
            float z1 = actf(f1 + fbv, g1 + gbv);
            const size_t oo = ((size_t)b * C + co) * T + t;
            float2 v = make_float2(z0, z1);
            if (!first) {
                float2 p = *(const float2*)(out + oo);
                v.x += p.x; v.y += p.y;
            }
            *(float2*)(out + oo) = v;
            if (wnext) {
                const size_t zb = ((size_t)b * T + t) * C + co;
                split_bf(z0, zh[zb], zl[zb]);
                split_bf(z1, zh[zb + C], zl[zb + C]);
            }
        }
    }
}

// ---------------- launch ----------------
extern "C" void kernel_launch(void* const* d_in, const int* in_sizes, int n_in,
                              void* d_out, int out_size)
{
    const float* ys = (const float*)d_in[0];
    const float* fb = (const float*)d_in[2];
    const float* fw = (const float*)d_in[1];
    const float* gw = (const float*)d_in[3];
    const float* gb = (const float*)d_in[4];
    float* out = (float*)d_out;

    cudaFuncSetAttribute(wn_gemm, cudaFuncAttributeMaxDynamicSharedMemorySize, SMEM_TOTAL);

    cvt_weights<<<(LAYERS * C * C * 2 + 255) / 256, 256>>>(fw, gw);
    cvt_x<<<dim3(T / 32, C / 32, B), dim3(32, 8)>>>(ys);

    dim3 grid(T / 128, B, 2);
    for (int l = 0; l < LAYERS; l++) {
        wn_gemm<<<grid, 256, SMEM_TOTAL>>>(
            fb + (size_t)l * C, gb + (size_t)l * C, out,
            l & 1, l, 1 << l,
            (l == 0) ? 1 : 0, (l != LAYERS - 1) ? 1 : 0);
    }
}